// round 3
// baseline (speedup 1.0000x reference)
#include <cuda_runtime.h>

// ---------------------------------------------------------------------------
// CubeAttention: N=20 cube, D=64, CAP=32, SCOPE=2 -> WIDTH=5, P=125 neighbors.
//   K[v] = se[v] @ Wk[96:], V[v] = se[v] @ Wv[96:], Q[v] = se[v] @ Wq + bq
//   k_rel[p] = relpos_flat[p] @ Wk[:96] + bk   (same for v_rel)
// Reference quirk (replicated exactly): with p = a*25 + b*5 + c,
//   data gather   at padded (x+b, y+a, z+c)  -> zero rows outside [2,21]
//   validity mask at padded (x+a, y+b, z+c)  -> valid iff all in [3,21]
// A mask-valid p whose gather coord is out of data range contributes
// k_rel/v_rel only (zero embedding row).
// ---------------------------------------------------------------------------

#define NV   8000      // 20^3 voxels
#define DCH  64
#define NP   125

__device__ float g_Q[NV * DCH];
__device__ float g_K[NV * DCH];
__device__ float g_V[NV * DCH];
__device__ float g_krel[NP * DCH];
__device__ float g_vrel[NP * DCH];

// ---------------------------------------------------------------------------
// Prep: Q/K/V projections. blockIdx.y selects tensor. Thread = (row, channel).
// ---------------------------------------------------------------------------
__global__ void __launch_bounds__(256) prep_kernel(
    const float* __restrict__ se,
    const float* __restrict__ Wq, const float* __restrict__ bq,
    const float* __restrict__ Wk, const float* __restrict__ Wv)
{
    int sel = blockIdx.y;
    int idx = blockIdx.x * 256 + threadIdx.x;        // 0 .. NV*64-1
    int row = idx >> 6;
    int c   = idx & 63;
    if (row >= NV) return;

    const float* W = (sel == 0) ? Wq : (sel == 1) ? (Wk + 96 * 64) : (Wv + 96 * 64);
    float acc = (sel == 0) ? bq[c] : 0.0f;
    const float* s = se + row * 64;
    #pragma unroll 16
    for (int k = 0; k < 64; k++)
        acc = fmaf(s[k], W[k * 64 + c], acc);

    float* out = (sel == 0) ? g_Q : (sel == 1) ? g_K : g_V;
    out[idx] = acc;
}

// ---------------------------------------------------------------------------
// Rel tables: k_rel / v_rel (125 x 64). Block = p, thread = channel.
// relpos_flat[p] = [rw[a], rw[b], rw[c]] with p = a*25 + b*5 + c.
// ---------------------------------------------------------------------------
__global__ void __launch_bounds__(64) rel_kernel(
    const float* __restrict__ rw,
    const float* __restrict__ Wk, const float* __restrict__ bk,
    const float* __restrict__ Wv, const float* __restrict__ bv)
{
    int p  = blockIdx.x;
    int ch = threadIdx.x;
    int a = p / 25, b = (p / 5) % 5, c = p % 5;

    float kk = bk[ch];
    float vv = bv[ch];
    #pragma unroll 8
    for (int j = 0; j < 32; j++) {
        float ra = rw[a * 32 + j];
        float rb = rw[b * 32 + j];
        float rc = rw[c * 32 + j];
        kk = fmaf(ra, Wk[j * 64 + ch], kk);
        kk = fmaf(rb, Wk[(32 + j) * 64 + ch], kk);
        kk = fmaf(rc, Wk[(64 + j) * 64 + ch], kk);
        vv = fmaf(ra, Wv[j * 64 + ch], vv);
        vv = fmaf(rb, Wv[(32 + j) * 64 + ch], vv);
        vv = fmaf(rc, Wv[(64 + j) * 64 + ch], vv);
    }
    g_krel[p * 64 + ch] = kk;
    g_vrel[p * 64 + ch] = vv;
}

// ---------------------------------------------------------------------------
// Fused attention. One block = one voxel, 128 threads (4 warps).
// nvs[p]: -1 = masked out; -2 = valid but zero-data gather; >=0 = data voxel.
// ---------------------------------------------------------------------------
__global__ void __launch_bounds__(128) attn_kernel(
    const float* __restrict__ Wo, const float* __restrict__ bo,
    float* __restrict__ out)
{
    int v = blockIdx.x;
    int z = v % 20;
    int y = (v / 20) % 20;
    int x = v / 400;

    __shared__ float qs[64];
    __shared__ float sc[NP];
    __shared__ int   nvs[NP];
    __shared__ float red[4];
    __shared__ float acc1[64];
    __shared__ float ts[64];

    int tid  = threadIdx.x;
    int lane = tid & 31;
    int warp = tid >> 5;

    if (tid < 64) qs[tid] = g_Q[v * 64 + tid];
    __syncthreads();

    // ---- Phase 1: logits (warp per neighbor p) ----
    for (int p = warp; p < NP; p += 4) {
        int a = p / 25, b = (p / 5) % 5, c = p % 5;

        // mask coords (unpadded): (x+a-2, y+b-2, z+c-2) each in [1,19]
        int mx = x + a - 2, my = y + b - 2, mz = z + c - 2;
        bool mvalid = (mx >= 1) & (mx <= 19) & (my >= 1) & (my <= 19)
                    & (mz >= 1) & (mz <= 19);

        // data coords (unpadded): (x+b-2, y+a-2, z+c-2) each in [0,19]
        int dx = x + b - 2, dy = y + a - 2, dz = z + c - 2;
        bool in_data = (dx >= 0) & (dx <= 19) & (dy >= 0) & (dy <= 19)
                     & (dz >= 0) & (dz <= 19);

        float logit = -1e9f;
        int nv = -1;
        if (mvalid) {
            const float* rr = g_krel + p * 64;
            float s = fmaf(qs[lane], rr[lane], qs[lane + 32] * rr[lane + 32]);
            if (in_data) {
                nv = (dx * 20 + dy) * 20 + dz;
                const float* kr = g_K + nv * 64;
                s = fmaf(qs[lane], kr[lane], s);
                s = fmaf(qs[lane + 32], kr[lane + 32], s);
            } else {
                nv = -2;
            }
            #pragma unroll
            for (int o = 16; o; o >>= 1)
                s += __shfl_xor_sync(0xffffffffu, s, o);
            logit = s;
        }
        if (lane == 0) { sc[p] = logit; nvs[p] = nv; }
    }
    __syncthreads();

    // ---- Phase 2: softmax over 125 entries ----
    float l = (tid < NP) ? sc[tid] : -1e30f;
    float m = l;
    #pragma unroll
    for (int o = 16; o; o >>= 1)
        m = fmaxf(m, __shfl_xor_sync(0xffffffffu, m, o));
    if (lane == 0) red[warp] = m;
    __syncthreads();
    m = fmaxf(fmaxf(red[0], red[1]), fmaxf(red[2], red[3]));

    float e = (tid < NP) ? __expf(l - m) : 0.0f;   // masked: exp(~-1e9) == 0
    float ssum = e;
    #pragma unroll
    for (int o = 16; o; o >>= 1)
        ssum += __shfl_xor_sync(0xffffffffu, ssum, o);
    __syncthreads();               // red reuse
    if (lane == 0) red[warp] = ssum;
    __syncthreads();
    ssum = (red[0] + red[1]) + (red[2] + red[3]);
    float inv = 1.0f / ssum;
    if (tid < NP) sc[tid] = e * inv;
    __syncthreads();

    // ---- Phase 3: weighted value accumulation ----
    int half = tid >> 6;           // 0: even p, 1: odd p
    int c    = tid & 63;
    float acc = 0.0f;
    for (int p = half; p < NP; p += 2) {
        int nv = nvs[p];
        if (nv != -1) {
            float val = g_vrel[p * 64 + c];
            if (nv >= 0) val += g_V[nv * 64 + c];
            acc = fmaf(sc[p], val, acc);
        }
    }
    if (half) acc1[c] = acc;
    __syncthreads();
    if (!half) ts[c] = acc + acc1[c];
    __syncthreads();

    // ---- Phase 4: output projection ----
    if (tid < 64) {
        float o = bo[tid];
        #pragma unroll 16
        for (int k = 0; k < 64; k++)
            o = fmaf(ts[k], Wo[k * 64 + tid], o);
        out[v * 64 + tid] = o;
    }
}

// ---------------------------------------------------------------------------
// Launch
// d_in: 0=spatial_embeddings 1=relpos_w 2=Wq 3=bq 4=Wk 5=bk 6=Wv 7=bv 8=Wo 9=bo
// ---------------------------------------------------------------------------
extern "C" void kernel_launch(void* const* d_in, const int* in_sizes, int n_in,
                              void* d_out, int out_size)
{
    const float* se = (const float*)d_in[0];
    const float* rw = (const float*)d_in[1];
    const float* Wq = (const float*)d_in[2];
    const float* bq = (const float*)d_in[3];
    const float* Wk = (const float*)d_in[4];
    const float* bk = (const float*)d_in[5];
    const float* Wv = (const float*)d_in[6];
    const float* bv = (const float*)d_in[7];
    const float* Wo = (const float*)d_in[8];
    const float* bo = (const float*)d_in[9];
    float* out = (float*)d_out;

    prep_kernel<<<dim3((NV * DCH + 255) / 256, 3), 256>>>(se, Wq, bq, Wk, Wv);
    rel_kernel<<<NP, 64>>>(rw, Wk, bk, Wv, bv);
    attn_kernel<<<NV, 128>>>(Wo, bo, out);
}